// round 10
// baseline (speedup 1.0000x reference)
#include <cuda_runtime.h>
#include <cuda_fp16.h>
#include <cstdint>

#define Bv 8
#define Tv 512
#define Mv 16
#define Dv 128
#define Pv 256
#define Hv 8
#define Ev 32
#define ROWS (Bv*Tv*Mv)   // 65536
#define MP 4096           // Mv*Pv: element stride between consecutive t

// Projected Q,K,V stored as fp16 hi/lo pairs (split done in GEMM epilogue).
// Q is pre-scaled by 1/sqrt(E). Layout: ((b*T+t)*M+m)*P + h*E + e
__device__ half g_qh[(size_t)ROWS * Pv];
__device__ half g_ql[(size_t)ROWS * Pv];
__device__ half g_kh[(size_t)ROWS * Pv];
__device__ half g_kl[(size_t)ROWS * Pv];
__device__ half g_vh[(size_t)ROWS * Pv];
__device__ half g_vl[(size_t)ROWS * Pv];

__device__ __forceinline__ void split2(float x, half& hi, half& lo) {
    hi = __float2half_rn(x);
    lo = __float2half_rn(x - __half2float(hi));
}
__device__ __forceinline__ void splitpack(float x, float y, uint32_t& hi, uint32_t& lo) {
    half hx, lx, hy, ly;
    split2(x, hx, lx);
    split2(y, hy, ly);
    __half2 h = __halves2half2(hx, hy);
    __half2 l = __halves2half2(lx, ly);
    hi = *(uint32_t*)&h;
    lo = *(uint32_t*)&l;
}
// D = A(16x16 f16, row) @ B(16x8 f16, col) + D (f32)
__device__ __forceinline__ void mma16816(float* c, const uint32_t* a, const uint32_t* b) {
    asm volatile(
        "mma.sync.aligned.m16n8k16.row.col.f32.f16.f16.f32 "
        "{%0,%1,%2,%3}, {%4,%5,%6,%7}, {%8,%9}, {%0,%1,%2,%3};\n"
        : "+f"(c[0]), "+f"(c[1]), "+f"(c[2]), "+f"(c[3])
        : "r"(a[0]), "r"(a[1]), "r"(a[2]), "r"(a[3]), "r"(b[0]), "r"(b[1]));
}
__device__ __forceinline__ void ldsm4(uint32_t* r, uint32_t a) {
    asm volatile("ldmatrix.sync.aligned.m8n8.x4.shared.b16 {%0,%1,%2,%3}, [%4];"
        : "=r"(r[0]), "=r"(r[1]), "=r"(r[2]), "=r"(r[3]) : "r"(a));
}
__device__ __forceinline__ void ldsm4t(uint32_t* r, uint32_t a) {
    asm volatile("ldmatrix.sync.aligned.m8n8.x4.trans.shared.b16 {%0,%1,%2,%3}, [%4];"
        : "=r"(r[0]), "=r"(r[1]), "=r"(r[2]), "=r"(r[3]) : "r"(a));
}
__device__ __forceinline__ uint32_t sm_u32(const void* p) {
    return (uint32_t)__cvta_generic_to_shared(p);
}

// ===========================================================================
// QKV GEMM via mma.m16n8k16 with fp16 hi/lo 3-term splits + ldmatrix frags.
// ===========================================================================
#define GLD 72
#define GEMM_SMEM (4 * 128 * GLD * 2)             // 73728 bytes

__global__ __launch_bounds__(256) void qkv_gemm_mma(
    const float* __restrict__ A,
    const float* __restrict__ Wq, const float* __restrict__ bq,
    const float* __restrict__ Wk, const float* __restrict__ bk,
    const float* __restrict__ Wv, const float* __restrict__ bv)
{
    extern __shared__ half sm[];
    half* Ahi = sm;                 // [128][GLD]
    half* Alo = Ahi + 128 * GLD;
    half* Bhi = Alo + 128 * GLD;    // [c][k]
    half* Blo = Bhi + 128 * GLD;

    const int which = blockIdx.z;
    const float* __restrict__ W    = (which == 0) ? Wq : (which == 1) ? Wk : Wv;
    const float* __restrict__ bias = (which == 0) ? bq : (which == 1) ? bk : bv;
    half* __restrict__ Chi         = (which == 0) ? g_qh : (which == 1) ? g_kh : g_vh;
    half* __restrict__ Clo         = (which == 0) ? g_ql : (which == 1) ? g_kl : g_vl;
    const float oscale = (which == 0) ? 0.17677669529663687f : 1.0f;

    const int tid  = threadIdx.x;
    const int w    = tid >> 5;
    const int lane = tid & 31;
    const int g    = lane >> 2;
    const int c2   = (lane & 3) * 2;
    const int r8   = lane & 7;
    const int sel  = lane >> 3;          // 0..3
    const int rowBase = blockIdx.x * 128;
    const int colBase = blockIdx.y * 128;

    // per-thread ldmatrix base pointers
    const half* paH = Ahi + (size_t)(w * 16 + (sel & 1) * 8 + r8) * GLD + (sel >> 1) * 8;
    const half* paL = Alo + (size_t)(w * 16 + (sel & 1) * 8 + r8) * GLD + (sel >> 1) * 8;
    const half* pb0 = ((sel < 2) ? Bhi : Blo) + (size_t)r8 * GLD + (sel & 1) * 8;

    float acc[16][4];
    #pragma unroll
    for (int nb = 0; nb < 16; nb++)
        acc[nb][0] = acc[nb][1] = acc[nb][2] = acc[nb][3] = 0.f;

    for (int kk = 0; kk < Dv; kk += 64) {
        __syncthreads();
        for (int i = tid; i < 128 * 16; i += 256) {
            int r = i >> 4, k4 = (i & 15) * 4;
            float4 a = *(const float4*)&A[(size_t)(rowBase + r) * Dv + kk + k4];
            uint32_t h0, l0, h1, l1;
            splitpack(a.x, a.y, h0, l0);
            splitpack(a.z, a.w, h1, l1);
            *(uint32_t*)&Ahi[r * GLD + k4]     = h0;
            *(uint32_t*)&Ahi[r * GLD + k4 + 2] = h1;
            *(uint32_t*)&Alo[r * GLD + k4]     = l0;
            *(uint32_t*)&Alo[r * GLD + k4 + 2] = l1;
        }
        for (int i = tid; i < 128 * 16; i += 256) {
            int c = i >> 4, k4 = (i & 15) * 4;
            float w0 = W[(size_t)(kk + k4 + 0) * Pv + colBase + c];
            float w1 = W[(size_t)(kk + k4 + 1) * Pv + colBase + c];
            float w2 = W[(size_t)(kk + k4 + 2) * Pv + colBase + c];
            float w3 = W[(size_t)(kk + k4 + 3) * Pv + colBase + c];
            uint32_t h0, l0, h1, l1;
            splitpack(w0, w1, h0, l0);
            splitpack(w2, w3, h1, l1);
            *(uint32_t*)&Bhi[c * GLD + k4]     = h0;
            *(uint32_t*)&Bhi[c * GLD + k4 + 2] = h1;
            *(uint32_t*)&Blo[c * GLD + k4]     = l0;
            *(uint32_t*)&Blo[c * GLD + k4 + 2] = l1;
        }
        __syncthreads();

        #pragma unroll
        for (int ks = 0; ks < 4; ks++) {
            uint32_t ah[4], al[4];
            ldsm4(ah, sm_u32(paH + ks * 16));
            ldsm4(al, sm_u32(paL + ks * 16));
            #pragma unroll
            for (int nb = 0; nb < 16; nb++) {
                uint32_t f[4];
                ldsm4(f, sm_u32(pb0 + nb * 8 * GLD + ks * 16));
                mma16816(acc[nb], ah, f);
                mma16816(acc[nb], ah, f + 2);
                mma16816(acc[nb], al, f);
            }
        }
    }

    const int r0 = rowBase + w * 16 + g;
    const int r1 = r0 + 8;
    #pragma unroll
    for (int nb = 0; nb < 16; nb++) {
        int col = colBase + nb * 8 + c2;
        float bx = __ldg(&bias[col]);
        float by = __ldg(&bias[col + 1]);
        float v00 = (acc[nb][0] + bx) * oscale, v01 = (acc[nb][1] + by) * oscale;
        float v10 = (acc[nb][2] + bx) * oscale, v11 = (acc[nb][3] + by) * oscale;
        uint32_t h0, l0, h1, l1;
        splitpack(v00, v01, h0, l0);
        splitpack(v10, v11, h1, l1);
        *(uint32_t*)&Chi[(size_t)r0 * Pv + col] = h0;
        *(uint32_t*)&Clo[(size_t)r0 * Pv + col] = l0;
        *(uint32_t*)&Chi[(size_t)r1 * Pv + col] = h1;
        *(uint32_t*)&Clo[(size_t)r1 * Pv + col] = l1;
    }
}

// ---------------------------------------------------------------------------
// Flash attention: pre-split Q/K/V, ldmatrix fragment loads.
// K smem [key][e] -> B-frags via ldmatrix.x4 (hi+lo in one op).
// V smem [key][e] row-major -> B-frags via ldmatrix.x4.trans (no transpose STS).
// ---------------------------------------------------------------------------
__global__ __launch_bounds__(256) void attn_mma(
    const int* __restrict__ mask, float* __restrict__ out)
{
    __shared__ half Ksm[2][64][40];   // [hi/lo][key][e]
    __shared__ half Vsm[2][64][40];
    __shared__ float msk[64];

    const int tid  = threadIdx.x;
    const int w    = tid >> 5;
    const int lane = tid & 31;
    const int g    = lane >> 2;
    const int c2   = (lane & 3) * 2;
    const int r8   = lane & 7;
    const int sel  = lane >> 3;          // 0..3
    const int qt   = blockIdx.x;
    const int bmh  = blockIdx.y;
    const int h  = bmh & (Hv - 1);
    const int m_ = (bmh >> 3) & (Mv - 1);
    const int b  = bmh >> 7;

    const size_t base = ((size_t)b * Tv * Mv + m_) * (size_t)Pv + (size_t)h * Ev;
    const int qrow = qt * 128 + w * 16 + g;

    // ldmatrix per-thread base addresses (bytes)
    // K (no trans): group 0/1 -> hi (k cols 0-7 / 8-15), 2/3 -> lo
    const uint32_t kbase = sm_u32(&Ksm[sel >> 1][r8][(sel & 1) * 8]);
    // V (trans): group 0/1 -> hi rows +0/+8, 2/3 -> lo
    const uint32_t vbase = sm_u32(&Vsm[sel >> 1][(sel & 1) * 8 + r8][0]);

    // ---- Q fragments: direct half2 loads (scale already folded) ----
    uint32_t qh[2][4], ql[2][4];
    {
        const size_t o0 = base + (size_t)qrow * MP;
        const size_t o1 = o0 + (size_t)8 * MP;
        #pragma unroll
        for (int ks = 0; ks < 2; ks++) {
            int c = ks * 16 + c2;
            qh[ks][0] = *(const uint32_t*)&g_qh[o0 + c];
            qh[ks][1] = *(const uint32_t*)&g_qh[o1 + c];
            qh[ks][2] = *(const uint32_t*)&g_qh[o0 + c + 8];
            qh[ks][3] = *(const uint32_t*)&g_qh[o1 + c + 8];
            ql[ks][0] = *(const uint32_t*)&g_ql[o0 + c];
            ql[ks][1] = *(const uint32_t*)&g_ql[o1 + c];
            ql[ks][2] = *(const uint32_t*)&g_ql[o0 + c + 8];
            ql[ks][3] = *(const uint32_t*)&g_ql[o1 + c + 8];
        }
    }

    float O[4][4] = {};
    float mrow0 = -1e30f, mrow1 = -1e30f;
    float lrow0 = 0.f,    lrow1 = 0.f;

    for (int kt = 0; kt < 8; kt++) {
        __syncthreads();
        // stage 64 keys: all row-major, vectorized
        for (int i = tid; i < 64 * 8; i += 256) {
            int row = i >> 3, e4 = (i & 7) * 4;
            size_t off = base + (size_t)(kt * 64 + row) * MP + e4;
            *(uint2*)&Ksm[0][row][e4] = *(const uint2*)&g_kh[off];
            *(uint2*)&Ksm[1][row][e4] = *(const uint2*)&g_kl[off];
            *(uint2*)&Vsm[0][row][e4] = *(const uint2*)&g_vh[off];
            *(uint2*)&Vsm[1][row][e4] = *(const uint2*)&g_vl[off];
        }
        if (tid < 64)
            msk[tid] = mask[(size_t)(b * Tv + kt * 64 + tid) * Mv + m_] ? 1.f : 0.f;
        __syncthreads();

        // ---- S = Qs @ K^T ----
        float S[8][4];
        #pragma unroll
        for (int nb = 0; nb < 8; nb++) {
            S[nb][0] = S[nb][1] = S[nb][2] = S[nb][3] = 0.f;
            #pragma unroll
            for (int ks = 0; ks < 2; ks++) {
                uint32_t f[4];   // {bh0, bh1, bl0, bl1}
                ldsm4(f, kbase + (uint32_t)(nb * 640 + ks * 32));
                mma16816(S[nb], qh[ks], f);
                mma16816(S[nb], qh[ks], f + 2);
                mma16816(S[nb], ql[ks], f);
            }
        }

        // ---- mask + online softmax ----
        float mt0 = -1e30f, mt1 = -1e30f;
        #pragma unroll
        for (int nb = 0; nb < 8; nb++) {
            float mk0 = msk[nb * 8 + c2];
            float mk1 = msk[nb * 8 + c2 + 1];
            S[nb][0] = (mk0 != 0.f) ? S[nb][0] : -1e30f;
            S[nb][1] = (mk1 != 0.f) ? S[nb][1] : -1e30f;
            S[nb][2] = (mk0 != 0.f) ? S[nb][2] : -1e30f;
            S[nb][3] = (mk1 != 0.f) ? S[nb][3] : -1e30f;
            mt0 = fmaxf(mt0, fmaxf(S[nb][0], S[nb][1]));
            mt1 = fmaxf(mt1, fmaxf(S[nb][2], S[nb][3]));
        }
        mt0 = fmaxf(mt0, __shfl_xor_sync(0xffffffffu, mt0, 1));
        mt0 = fmaxf(mt0, __shfl_xor_sync(0xffffffffu, mt0, 2));
        mt1 = fmaxf(mt1, __shfl_xor_sync(0xffffffffu, mt1, 1));
        mt1 = fmaxf(mt1, __shfl_xor_sync(0xffffffffu, mt1, 2));

        float mn0 = fmaxf(mrow0, mt0), mn1 = fmaxf(mrow1, mt1);
        float a0 = __expf(mrow0 - mn0), a1 = __expf(mrow1 - mn1);
        mrow0 = mn0; mrow1 = mn1;

        float rs0 = 0.f, rs1 = 0.f;
        #pragma unroll
        for (int nb = 0; nb < 8; nb++) {
            S[nb][0] = __expf(S[nb][0] - mn0);
            S[nb][1] = __expf(S[nb][1] - mn0);
            S[nb][2] = __expf(S[nb][2] - mn1);
            S[nb][3] = __expf(S[nb][3] - mn1);
            rs0 += S[nb][0] + S[nb][1];
            rs1 += S[nb][2] + S[nb][3];
        }
        rs0 += __shfl_xor_sync(0xffffffffu, rs0, 1);
        rs0 += __shfl_xor_sync(0xffffffffu, rs0, 2);
        rs1 += __shfl_xor_sync(0xffffffffu, rs1, 1);
        rs1 += __shfl_xor_sync(0xffffffffu, rs1, 2);
        lrow0 = lrow0 * a0 + rs0;
        lrow1 = lrow1 * a1 + rs1;
        #pragma unroll
        for (int eb = 0; eb < 4; eb++) {
            O[eb][0] *= a0; O[eb][1] *= a0;
            O[eb][2] *= a1; O[eb][3] *= a1;
        }

        // ---- O += P @ V (V B-frags via ldmatrix.trans) ----
        #pragma unroll
        for (int kb = 0; kb < 4; kb++) {
            uint32_t ph[4], pl[4];
            splitpack(S[2 * kb][0],     S[2 * kb][1],     ph[0], pl[0]);
            splitpack(S[2 * kb][2],     S[2 * kb][3],     ph[1], pl[1]);
            splitpack(S[2 * kb + 1][0], S[2 * kb + 1][1], ph[2], pl[2]);
            splitpack(S[2 * kb + 1][2], S[2 * kb + 1][3], ph[3], pl[3]);
            #pragma unroll
            for (int eb = 0; eb < 4; eb++) {
                uint32_t f[4];   // {vh0, vh1, vl0, vl1}
                ldsm4t(f, vbase + (uint32_t)(kb * 1280 + eb * 16));
                mma16816(O[eb], ph, f);
                mma16816(O[eb], ph, f + 2);
                mma16816(O[eb], pl, f);
            }
        }
    }

    float inv0 = (mrow0 > -1e29f) ? (1.f / lrow0) : 0.f;
    float inv1 = (mrow1 > -1e29f) ? (1.f / lrow1) : 0.f;
    float* o0 = &out[base + (size_t)qrow * MP];
    float* o1 = o0 + (size_t)8 * MP;
    #pragma unroll
    for (int eb = 0; eb < 4; eb++) {
        int e = eb * 8 + c2;
        o0[e]     = O[eb][0] * inv0;
        o0[e + 1] = O[eb][1] * inv0;
        o1[e]     = O[eb][2] * inv1;
        o1[e + 1] = O[eb][3] * inv1;
    }
}

// ---------------------------------------------------------------------------
// Inputs (metadata order): inp, mask, Wq, bq, Wk, bk, Wv, bv
// ---------------------------------------------------------------------------
extern "C" void kernel_launch(void* const* d_in, const int* in_sizes, int n_in,
                              void* d_out, int out_size)
{
    (void)in_sizes; (void)n_in; (void)out_size;
    const float* inp  = (const float*)d_in[0];
    const int*   mask = (const int*)d_in[1];
    const float* Wq = (const float*)d_in[2];
    const float* bq = (const float*)d_in[3];
    const float* Wk = (const float*)d_in[4];
    const float* bk = (const float*)d_in[5];
    const float* Wv = (const float*)d_in[6];
    const float* bv = (const float*)d_in[7];
    float* out = (float*)d_out;

    static bool attr_done = false;
    if (!attr_done) {
        cudaFuncSetAttribute(qkv_gemm_mma, cudaFuncAttributeMaxDynamicSharedMemorySize, GEMM_SMEM);
        attr_done = true;
    }

    dim3 ggrid(ROWS / 128, Pv / 128, 3);   // (512, 2, 3)
    qkv_gemm_mma<<<ggrid, 256, GEMM_SMEM>>>(inp, Wq, bq, Wk, bk, Wv, bv);

    dim3 agrid(Tv / 128, Bv * Mv * Hv);    // (4, 1024)
    attn_mma<<<agrid, 256>>>(mask, out);
}

// round 11
// speedup vs baseline: 1.2347x; 1.2347x over previous
#include <cuda_runtime.h>
#include <cuda_fp16.h>
#include <cstdint>

#define Bv 8
#define Tv 512
#define Mv 16
#define Dv 128
#define Pv 256
#define Hv 8
#define Ev 32
#define ROWS (Bv*Tv*Mv)   // 65536
#define MP 4096           // Mv*Pv: element stride between consecutive t

// Projected Q,K,V stored as fp16 hi/lo pairs (split done in GEMM epilogue).
// Q is pre-scaled by 1/sqrt(E). Layout: ((b*T+t)*M+m)*P + h*E + e
__device__ half g_qh[(size_t)ROWS * Pv];
__device__ half g_ql[(size_t)ROWS * Pv];
__device__ half g_kh[(size_t)ROWS * Pv];
__device__ half g_kl[(size_t)ROWS * Pv];
__device__ half g_vh[(size_t)ROWS * Pv];
__device__ half g_vl[(size_t)ROWS * Pv];

__device__ __forceinline__ void split2(float x, half& hi, half& lo) {
    hi = __float2half_rn(x);
    lo = __float2half_rn(x - __half2float(hi));
}
__device__ __forceinline__ void splitpack(float x, float y, uint32_t& hi, uint32_t& lo) {
    half hx, lx, hy, ly;
    split2(x, hx, lx);
    split2(y, hy, ly);
    __half2 h = __halves2half2(hx, hy);
    __half2 l = __halves2half2(lx, ly);
    hi = *(uint32_t*)&h;
    lo = *(uint32_t*)&l;
}
__device__ __forceinline__ void mma16816(float* c, const uint32_t* a, const uint32_t* b) {
    asm volatile(
        "mma.sync.aligned.m16n8k16.row.col.f32.f16.f16.f32 "
        "{%0,%1,%2,%3}, {%4,%5,%6,%7}, {%8,%9}, {%0,%1,%2,%3};\n"
        : "+f"(c[0]), "+f"(c[1]), "+f"(c[2]), "+f"(c[3])
        : "r"(a[0]), "r"(a[1]), "r"(a[2]), "r"(a[3]), "r"(b[0]), "r"(b[1]));
}
__device__ __forceinline__ void ldsm4(uint32_t* r, uint32_t a) {
    asm volatile("ldmatrix.sync.aligned.m8n8.x4.shared.b16 {%0,%1,%2,%3}, [%4];"
        : "=r"(r[0]), "=r"(r[1]), "=r"(r[2]), "=r"(r[3]) : "r"(a));
}
__device__ __forceinline__ void ldsm4t(uint32_t* r, uint32_t a) {
    asm volatile("ldmatrix.sync.aligned.m8n8.x4.trans.shared.b16 {%0,%1,%2,%3}, [%4];"
        : "=r"(r[0]), "=r"(r[1]), "=r"(r[2]), "=r"(r[3]) : "r"(a));
}
__device__ __forceinline__ uint32_t sm_u32(const void* p) {
    return (uint32_t)__cvta_generic_to_shared(p);
}
__device__ __forceinline__ void cp16(uint32_t dst, const void* src) {
    asm volatile("cp.async.cg.shared.global [%0], [%1], 16;" :: "r"(dst), "l"(src));
}
__device__ __forceinline__ void cp_commit() {
    asm volatile("cp.async.commit_group;");
}
template<int N>
__device__ __forceinline__ void cp_wait() {
    asm volatile("cp.async.wait_group %0;" :: "n"(N));
}

// ===========================================================================
// QKV GEMM via mma.m16n8k16 with fp16 hi/lo 3-term splits (R9 inner loop).
// Epilogue writes hi/lo half arrays (Q pre-scaled).
// ===========================================================================
#define GLD 72
#define GEMM_SMEM (4 * 128 * GLD * 2)             // 73728 bytes

__global__ __launch_bounds__(256) void qkv_gemm_mma(
    const float* __restrict__ A,
    const float* __restrict__ Wq, const float* __restrict__ bq,
    const float* __restrict__ Wk, const float* __restrict__ bk,
    const float* __restrict__ Wv, const float* __restrict__ bv)
{
    extern __shared__ half sm[];
    half* Ahi = sm;                 // [128][GLD]
    half* Alo = Ahi + 128 * GLD;
    half* Bhi = Alo + 128 * GLD;    // [c][k]
    half* Blo = Bhi + 128 * GLD;

    const int which = blockIdx.z;
    const float* __restrict__ W    = (which == 0) ? Wq : (which == 1) ? Wk : Wv;
    const float* __restrict__ bias = (which == 0) ? bq : (which == 1) ? bk : bv;
    half* __restrict__ Chi         = (which == 0) ? g_qh : (which == 1) ? g_kh : g_vh;
    half* __restrict__ Clo         = (which == 0) ? g_ql : (which == 1) ? g_kl : g_vl;
    const float oscale = (which == 0) ? 0.17677669529663687f : 1.0f;

    const int tid  = threadIdx.x;
    const int w    = tid >> 5;
    const int lane = tid & 31;
    const int g    = lane >> 2;
    const int c2   = (lane & 3) * 2;
    const int rowBase = blockIdx.x * 128;
    const int colBase = blockIdx.y * 128;

    float acc[16][4];
    #pragma unroll
    for (int nb = 0; nb < 16; nb++)
        acc[nb][0] = acc[nb][1] = acc[nb][2] = acc[nb][3] = 0.f;

    for (int kk = 0; kk < Dv; kk += 64) {
        __syncthreads();
        for (int i = tid; i < 128 * 16; i += 256) {
            int r = i >> 4, k4 = (i & 15) * 4;
            float4 a = *(const float4*)&A[(size_t)(rowBase + r) * Dv + kk + k4];
            uint32_t h0, l0, h1, l1;
            splitpack(a.x, a.y, h0, l0);
            splitpack(a.z, a.w, h1, l1);
            *(uint32_t*)&Ahi[r * GLD + k4]     = h0;
            *(uint32_t*)&Ahi[r * GLD + k4 + 2] = h1;
            *(uint32_t*)&Alo[r * GLD + k4]     = l0;
            *(uint32_t*)&Alo[r * GLD + k4 + 2] = l1;
        }
        for (int i = tid; i < 128 * 16; i += 256) {
            int c = i >> 4, k4 = (i & 15) * 4;
            float w0 = W[(size_t)(kk + k4 + 0) * Pv + colBase + c];
            float w1 = W[(size_t)(kk + k4 + 1) * Pv + colBase + c];
            float w2 = W[(size_t)(kk + k4 + 2) * Pv + colBase + c];
            float w3 = W[(size_t)(kk + k4 + 3) * Pv + colBase + c];
            uint32_t h0, l0, h1, l1;
            splitpack(w0, w1, h0, l0);
            splitpack(w2, w3, h1, l1);
            *(uint32_t*)&Bhi[c * GLD + k4]     = h0;
            *(uint32_t*)&Bhi[c * GLD + k4 + 2] = h1;
            *(uint32_t*)&Blo[c * GLD + k4]     = l0;
            *(uint32_t*)&Blo[c * GLD + k4 + 2] = l1;
        }
        __syncthreads();

        #pragma unroll
        for (int ks = 0; ks < 4; ks++) {
            uint32_t ah[4], al[4];
            const half* a0 = &Ahi[(w * 16 + g) * GLD + ks * 16 + c2];
            const half* a1 = a0 + 8 * GLD;
            ah[0] = *(const uint32_t*)a0;
            ah[1] = *(const uint32_t*)a1;
            ah[2] = *(const uint32_t*)(a0 + 8);
            ah[3] = *(const uint32_t*)(a1 + 8);
            const half* b0 = &Alo[(w * 16 + g) * GLD + ks * 16 + c2];
            const half* b1 = b0 + 8 * GLD;
            al[0] = *(const uint32_t*)b0;
            al[1] = *(const uint32_t*)b1;
            al[2] = *(const uint32_t*)(b0 + 8);
            al[3] = *(const uint32_t*)(b1 + 8);

            #pragma unroll
            for (int nb = 0; nb < 16; nb++) {
                uint32_t bh[2], bl[2];
                const half* bp = &Bhi[(nb * 8 + g) * GLD + ks * 16 + c2];
                bh[0] = *(const uint32_t*)bp;
                bh[1] = *(const uint32_t*)(bp + 8);
                const half* lp = &Blo[(nb * 8 + g) * GLD + ks * 16 + c2];
                bl[0] = *(const uint32_t*)lp;
                bl[1] = *(const uint32_t*)(lp + 8);
                mma16816(acc[nb], ah, bh);
                mma16816(acc[nb], ah, bl);
                mma16816(acc[nb], al, bh);
            }
        }
    }

    const int r0 = rowBase + w * 16 + g;
    const int r1 = r0 + 8;
    #pragma unroll
    for (int nb = 0; nb < 16; nb++) {
        int col = colBase + nb * 8 + c2;
        float bx = __ldg(&bias[col]);
        float by = __ldg(&bias[col + 1]);
        float v00 = (acc[nb][0] + bx) * oscale, v01 = (acc[nb][1] + by) * oscale;
        float v10 = (acc[nb][2] + bx) * oscale, v11 = (acc[nb][3] + by) * oscale;
        uint32_t h0, l0, h1, l1;
        splitpack(v00, v01, h0, l0);
        splitpack(v10, v11, h1, l1);
        *(uint32_t*)&Chi[(size_t)r0 * Pv + col] = h0;
        *(uint32_t*)&Clo[(size_t)r0 * Pv + col] = l0;
        *(uint32_t*)&Chi[(size_t)r1 * Pv + col] = h1;
        *(uint32_t*)&Clo[(size_t)r1 * Pv + col] = l1;
    }
}

// ---------------------------------------------------------------------------
// Flash attention: pre-split Q/K/V, ldmatrix frags, cp.async double buffering.
// ---------------------------------------------------------------------------
__global__ __launch_bounds__(256) void attn_mma(
    const int* __restrict__ mask, float* __restrict__ out)
{
    __shared__ half Ksm[2][2][64][40];   // [buf][hi/lo][key][e]
    __shared__ half Vsm[2][2][64][40];
    __shared__ float msk[Tv];

    const int tid  = threadIdx.x;
    const int w    = tid >> 5;
    const int lane = tid & 31;
    const int g    = lane >> 2;
    const int c2   = (lane & 3) * 2;
    const int r8   = lane & 7;
    const int sel  = lane >> 3;          // 0..3
    const int qt   = blockIdx.x;
    const int bmh  = blockIdx.y;
    const int h  = bmh & (Hv - 1);
    const int m_ = (bmh >> 3) & (Mv - 1);
    const int b  = bmh >> 7;

    const size_t base = ((size_t)b * Tv * Mv + m_) * (size_t)Pv + (size_t)h * Ev;
    const int qrow = qt * 128 + w * 16 + g;

    // cp.async staging map: thread -> (row, chunk); one 16B chunk per array
    const int srow = tid >> 2;
    const int se8  = (tid & 3) * 8;

    // ldmatrix per-thread base addresses per buffer
    uint32_t kbase[2], vbase[2];
    #pragma unroll
    for (int bf = 0; bf < 2; bf++) {
        kbase[bf] = sm_u32(&Ksm[bf][sel >> 1][r8][(sel & 1) * 8]);
        vbase[bf] = sm_u32(&Vsm[bf][sel >> 1][(sel & 1) * 8 + r8][0]);
    }

    // ---- mask preload (whole row of 512) ----
    for (int i = tid; i < Tv; i += 256)
        msk[i] = mask[(size_t)(b * Tv + i) * Mv + m_] ? 1.f : 0.f;

    // ---- Q fragments ----
    uint32_t qh[2][4], ql[2][4];
    {
        const size_t o0 = base + (size_t)qrow * MP;
        const size_t o1 = o0 + (size_t)8 * MP;
        #pragma unroll
        for (int ks = 0; ks < 2; ks++) {
            int c = ks * 16 + c2;
            qh[ks][0] = *(const uint32_t*)&g_qh[o0 + c];
            qh[ks][1] = *(const uint32_t*)&g_qh[o1 + c];
            qh[ks][2] = *(const uint32_t*)&g_qh[o0 + c + 8];
            qh[ks][3] = *(const uint32_t*)&g_qh[o1 + c + 8];
            ql[ks][0] = *(const uint32_t*)&g_ql[o0 + c];
            ql[ks][1] = *(const uint32_t*)&g_ql[o1 + c];
            ql[ks][2] = *(const uint32_t*)&g_ql[o0 + c + 8];
            ql[ks][3] = *(const uint32_t*)&g_ql[o1 + c + 8];
        }
    }

    // stage key-tile kt into buffer bf (issue only; no commit)
    auto stage = [&](int kt, int bf) {
        size_t off = base + (size_t)(kt * 64 + srow) * MP + se8;
        cp16(sm_u32(&Ksm[bf][0][srow][se8]), &g_kh[off]);
        cp16(sm_u32(&Ksm[bf][1][srow][se8]), &g_kl[off]);
        cp16(sm_u32(&Vsm[bf][0][srow][se8]), &g_vh[off]);
        cp16(sm_u32(&Vsm[bf][1][srow][se8]), &g_vl[off]);
    };

    float O[4][4] = {};
    float mrow0 = -1e30f, mrow1 = -1e30f;
    float lrow0 = 0.f,    lrow1 = 0.f;

    stage(0, 0);
    cp_commit();

    for (int kt = 0; kt < 8; kt++) {
        const int cur = kt & 1;
        if (kt < 7) {
            stage(kt + 1, cur ^ 1);
            cp_commit();
            cp_wait<1>();
        } else {
            cp_wait<0>();
        }
        __syncthreads();

        // ---- S = Qs @ K^T ----
        float S[8][4];
        #pragma unroll
        for (int nb = 0; nb < 8; nb++) {
            S[nb][0] = S[nb][1] = S[nb][2] = S[nb][3] = 0.f;
            #pragma unroll
            for (int ks = 0; ks < 2; ks++) {
                uint32_t f[4];   // {bh0, bh1, bl0, bl1}
                ldsm4(f, kbase[cur] + (uint32_t)(nb * 640 + ks * 32));
                mma16816(S[nb], qh[ks], f);
                mma16816(S[nb], qh[ks], f + 2);
                mma16816(S[nb], ql[ks], f);
            }
        }

        // ---- mask + online softmax ----
        const float* mrow = &msk[kt * 64];
        float mt0 = -1e30f, mt1 = -1e30f;
        #pragma unroll
        for (int nb = 0; nb < 8; nb++) {
            float mk0 = mrow[nb * 8 + c2];
            float mk1 = mrow[nb * 8 + c2 + 1];
            S[nb][0] = (mk0 != 0.f) ? S[nb][0] : -1e30f;
            S[nb][1] = (mk1 != 0.f) ? S[nb][1] : -1e30f;
            S[nb][2] = (mk0 != 0.f) ? S[nb][2] : -1e30f;
            S[nb][3] = (mk1 != 0.f) ? S[nb][3] : -1e30f;
            mt0 = fmaxf(mt0, fmaxf(S[nb][0], S[nb][1]));
            mt1 = fmaxf(mt1, fmaxf(S[nb][2], S[nb][3]));
        }
        mt0 = fmaxf(mt0, __shfl_xor_sync(0xffffffffu, mt0, 1));
        mt0 = fmaxf(mt0, __shfl_xor_sync(0xffffffffu, mt0, 2));
        mt1 = fmaxf(mt1, __shfl_xor_sync(0xffffffffu, mt1, 1));
        mt1 = fmaxf(mt1, __shfl_xor_sync(0xffffffffu, mt1, 2));

        float mn0 = fmaxf(mrow0, mt0), mn1 = fmaxf(mrow1, mt1);
        float a0 = __expf(mrow0 - mn0), a1 = __expf(mrow1 - mn1);
        mrow0 = mn0; mrow1 = mn1;

        float rs0 = 0.f, rs1 = 0.f;
        #pragma unroll
        for (int nb = 0; nb < 8; nb++) {
            S[nb][0] = __expf(S[nb][0] - mn0);
            S[nb][1] = __expf(S[nb][1] - mn0);
            S[nb][2] = __expf(S[nb][2] - mn1);
            S[nb][3] = __expf(S[nb][3] - mn1);
            rs0 += S[nb][0] + S[nb][1];
            rs1 += S[nb][2] + S[nb][3];
        }
        rs0 += __shfl_xor_sync(0xffffffffu, rs0, 1);
        rs0 += __shfl_xor_sync(0xffffffffu, rs0, 2);
        rs1 += __shfl_xor_sync(0xffffffffu, rs1, 1);
        rs1 += __shfl_xor_sync(0xffffffffu, rs1, 2);
        lrow0 = lrow0 * a0 + rs0;
        lrow1 = lrow1 * a1 + rs1;
        #pragma unroll
        for (int eb = 0; eb < 4; eb++) {
            O[eb][0] *= a0; O[eb][1] *= a0;
            O[eb][2] *= a1; O[eb][3] *= a1;
        }

        // ---- O += P @ V (V B-frags via ldmatrix.trans) ----
        #pragma unroll
        for (int kb = 0; kb < 4; kb++) {
            uint32_t ph[4], pl[4];
            splitpack(S[2 * kb][0],     S[2 * kb][1],     ph[0], pl[0]);
            splitpack(S[2 * kb][2],     S[2 * kb][3],     ph[1], pl[1]);
            splitpack(S[2 * kb + 1][0], S[2 * kb + 1][1], ph[2], pl[2]);
            splitpack(S[2 * kb + 1][2], S[2 * kb + 1][3], ph[3], pl[3]);
            #pragma unroll
            for (int eb = 0; eb < 4; eb++) {
                uint32_t f[4];   // {vh0, vh1, vl0, vl1}
                ldsm4t(f, vbase[cur] + (uint32_t)(kb * 1280 + eb * 16));
                mma16816(O[eb], ph, f);
                mma16816(O[eb], ph, f + 2);
                mma16816(O[eb], pl, f);
            }
        }
        __syncthreads();   // all warps done with buf cur before it is re-staged
    }

    float inv0 = (mrow0 > -1e29f) ? (1.f / lrow0) : 0.f;
    float inv1 = (mrow1 > -1e29f) ? (1.f / lrow1) : 0.f;
    float* o0 = &out[base + (size_t)qrow * MP];
    float* o1 = o0 + (size_t)8 * MP;
    #pragma unroll
    for (int eb = 0; eb < 4; eb++) {
        int e = eb * 8 + c2;
        o0[e]     = O[eb][0] * inv0;
        o0[e + 1] = O[eb][1] * inv0;
        o1[e]     = O[eb][2] * inv1;
        o1[e + 1] = O[eb][3] * inv1;
    }
}

// ---------------------------------------------------------------------------
// Inputs (metadata order): inp, mask, Wq, bq, Wk, bk, Wv, bv
// ---------------------------------------------------------------------------
extern "C" void kernel_launch(void* const* d_in, const int* in_sizes, int n_in,
                              void* d_out, int out_size)
{
    (void)in_sizes; (void)n_in; (void)out_size;
    const float* inp  = (const float*)d_in[0];
    const int*   mask = (const int*)d_in[1];
    const float* Wq = (const float*)d_in[2];
    const float* bq = (const float*)d_in[3];
    const float* Wk = (const float*)d_in[4];
    const float* bk = (const float*)d_in[5];
    const float* Wv = (const float*)d_in[6];
    const float* bv = (const float*)d_in[7];
    float* out = (float*)d_out;

    static bool attr_done = false;
    if (!attr_done) {
        cudaFuncSetAttribute(qkv_gemm_mma, cudaFuncAttributeMaxDynamicSharedMemorySize, GEMM_SMEM);
        attr_done = true;
    }

    dim3 ggrid(ROWS / 128, Pv / 128, 3);   // (512, 2, 3)
    qkv_gemm_mma<<<ggrid, 256, GEMM_SMEM>>>(inp, Wq, bq, Wk, bk, Wv, bv);

    dim3 agrid(Tv / 128, Bv * Mv * Hv);    // (4, 1024)
    attn_mma<<<agrid, 256>>>(mask, out);
}

// round 13
// speedup vs baseline: 1.4020x; 1.1355x over previous
#include <cuda_runtime.h>
#include <cuda_fp16.h>
#include <cstdint>

#define Bv 8
#define Tv 512
#define Mv 16
#define Dv 128
#define Pv 256
#define Hv 8
#define Ev 32
#define ROWS (Bv*Tv*Mv)   // 65536
#define MP 4096           // Mv*Pv: element stride between consecutive t

// Projected Q,K,V stored as fp16 hi/lo pairs. Q pre-scaled by 1/sqrt(E).
__device__ half g_qh[(size_t)ROWS * Pv];
__device__ half g_ql[(size_t)ROWS * Pv];
__device__ half g_kh[(size_t)ROWS * Pv];
__device__ half g_kl[(size_t)ROWS * Pv];
__device__ half g_vh[(size_t)ROWS * Pv];
__device__ half g_vl[(size_t)ROWS * Pv];
// Pre-split GEMM inputs: A (inp) hi/lo, W transposed [which][c][k] hi/lo.
__device__ half g_ah[(size_t)ROWS * Dv];
__device__ half g_al[(size_t)ROWS * Dv];
__device__ half g_wh[3 * Pv * Dv];
__device__ half g_wl[3 * Pv * Dv];

__device__ __forceinline__ void split2(float x, half& hi, half& lo) {
    hi = __float2half_rn(x);
    lo = __float2half_rn(x - __half2float(hi));
}
__device__ __forceinline__ void splitpack(float x, float y, uint32_t& hi, uint32_t& lo) {
    half hx, lx, hy, ly;
    split2(x, hx, lx);
    split2(y, hy, ly);
    __half2 h = __halves2half2(hx, hy);
    __half2 l = __halves2half2(lx, ly);
    hi = *(uint32_t*)&h;
    lo = *(uint32_t*)&l;
}
__device__ __forceinline__ void mma16816(float* c, const uint32_t* a, const uint32_t* b) {
    asm volatile(
        "mma.sync.aligned.m16n8k16.row.col.f32.f16.f16.f32 "
        "{%0,%1,%2,%3}, {%4,%5,%6,%7}, {%8,%9}, {%0,%1,%2,%3};\n"
        : "+f"(c[0]), "+f"(c[1]), "+f"(c[2]), "+f"(c[3])
        : "r"(a[0]), "r"(a[1]), "r"(a[2]), "r"(a[3]), "r"(b[0]), "r"(b[1]));
}
__device__ __forceinline__ void ldsm4(uint32_t* r, uint32_t a) {
    asm volatile("ldmatrix.sync.aligned.m8n8.x4.shared.b16 {%0,%1,%2,%3}, [%4];"
        : "=r"(r[0]), "=r"(r[1]), "=r"(r[2]), "=r"(r[3]) : "r"(a));
}
__device__ __forceinline__ void ldsm4t(uint32_t* r, uint32_t a) {
    asm volatile("ldmatrix.sync.aligned.m8n8.x4.trans.shared.b16 {%0,%1,%2,%3}, [%4];"
        : "=r"(r[0]), "=r"(r[1]), "=r"(r[2]), "=r"(r[3]) : "r"(a));
}
__device__ __forceinline__ uint32_t sm_u32(const void* p) {
    return (uint32_t)__cvta_generic_to_shared(p);
}
__device__ __forceinline__ void cp16(uint32_t dst, const void* src) {
    asm volatile("cp.async.cg.shared.global [%0], [%1], 16;" :: "r"(dst), "l"(src));
}
__device__ __forceinline__ void cp_commit() {
    asm volatile("cp.async.commit_group;");
}
template<int N>
__device__ __forceinline__ void cp_wait() {
    asm volatile("cp.async.wait_group %0;" :: "n"(N));
}

// ===========================================================================
// Prep: split inp -> hi/lo halfs (once, bandwidth-bound).
// ===========================================================================
__global__ __launch_bounds__(256) void prep_a(const float* __restrict__ inp)
{
    size_t idx = (size_t)blockIdx.x * 256 + threadIdx.x;   // over ROWS*Dv/4
    float4 a = *(const float4*)&inp[idx * 4];
    uint32_t h0, l0, h1, l1;
    splitpack(a.x, a.y, h0, l0);
    splitpack(a.z, a.w, h1, l1);
    *(uint32_t*)&g_ah[idx * 4]     = h0;
    *(uint32_t*)&g_ah[idx * 4 + 2] = h1;
    *(uint32_t*)&g_al[idx * 4]     = l0;
    *(uint32_t*)&g_al[idx * 4 + 2] = l1;
}

// Prep: W -> transposed [which][c][k] hi/lo.
__global__ __launch_bounds__(256) void prep_w(
    const float* __restrict__ Wq, const float* __restrict__ Wk, const float* __restrict__ Wv)
{
    int t = blockIdx.x * 256 + threadIdx.x;    // 3*256*32 = 24576 threads
    int which = t / 8192;
    int rem = t - which * 8192;
    int c  = rem >> 5;
    int k4 = (rem & 31) * 4;
    const float* W = (which == 0) ? Wq : (which == 1) ? Wk : Wv;
    float w0 = W[(size_t)(k4 + 0) * Pv + c];
    float w1 = W[(size_t)(k4 + 1) * Pv + c];
    float w2 = W[(size_t)(k4 + 2) * Pv + c];
    float w3 = W[(size_t)(k4 + 3) * Pv + c];
    uint32_t h0, l0, h1, l1;
    splitpack(w0, w1, h0, l0);
    splitpack(w2, w3, h1, l1);
    size_t off = ((size_t)which * Pv + c) * Dv + k4;
    *(uint32_t*)&g_wh[off]     = h0;
    *(uint32_t*)&g_wh[off + 2] = h1;
    *(uint32_t*)&g_wl[off]     = l0;
    *(uint32_t*)&g_wl[off + 2] = l1;
}

// ===========================================================================
// QKV GEMM: pre-split inputs, cp.async double-buffered tiles, ldmatrix frags.
// Block: 128x128 output tile, 256 threads. BK=64, 2 k-steps pipelined.
// ===========================================================================
#define GLD 72
#define GEMM_SMEM (8 * 128 * GLD * 2)   // sA[2][2][128][GLD] + sW[2][2][128][GLD] = 147456 B

__global__ __launch_bounds__(256) void qkv_gemm_mma(
    const float* __restrict__ bq, const float* __restrict__ bk, const float* __restrict__ bv)
{
    extern __shared__ half sm[];
    // sA[buf][hl][r][k], sW[buf][hl][c][k]
    half* sA = sm;                       // 2*2*128*GLD
    half* sW = sA + 4 * 128 * GLD;

    const int which = blockIdx.z;
    const float* __restrict__ bias = (which == 0) ? bq : (which == 1) ? bk : bv;
    half* __restrict__ Chi         = (which == 0) ? g_qh : (which == 1) ? g_kh : g_vh;
    half* __restrict__ Clo         = (which == 0) ? g_ql : (which == 1) ? g_kl : g_vl;
    const float oscale = (which == 0) ? 0.17677669529663687f : 1.0f;

    const int tid  = threadIdx.x;
    const int w    = tid >> 5;
    const int lane = tid & 31;
    const int g    = lane >> 2;
    const int c2   = (lane & 3) * 2;
    const int r8   = lane & 7;
    const int sel  = lane >> 3;
    const int rowBase = blockIdx.x * 128;
    const int colBase = blockIdx.y * 128;

    const size_t AR = 128 * GLD;   // one [128][GLD] array (halfs)

    // stage BK=64 tile into buffer bf: 128 rows x 8 chunks of 8 halfs per array
    auto stage = [&](int kk, int bf) {
        #pragma unroll
        for (int it = 0; it < 4; it++) {
            int i  = tid + it * 256;             // 0..1023
            int r  = i >> 3;                     // 0..127
            int k8 = (i & 7) * 8;                // 0..56 halfs
            size_t asrc = (size_t)(rowBase + r) * Dv + kk + k8;
            cp16(sm_u32(&sA[(size_t)(bf * 2 + 0) * AR + r * GLD + k8]), &g_ah[asrc]);
            cp16(sm_u32(&sA[(size_t)(bf * 2 + 1) * AR + r * GLD + k8]), &g_al[asrc]);
            size_t wsrc = ((size_t)which * Pv + colBase + r) * Dv + kk + k8;
            cp16(sm_u32(&sW[(size_t)(bf * 2 + 0) * AR + r * GLD + k8]), &g_wh[wsrc]);
            cp16(sm_u32(&sW[(size_t)(bf * 2 + 1) * AR + r * GLD + k8]), &g_wl[wsrc]);
        }
    };

    float acc[16][4];
    #pragma unroll
    for (int nb = 0; nb < 16; nb++)
        acc[nb][0] = acc[nb][1] = acc[nb][2] = acc[nb][3] = 0.f;

    // per-thread ldmatrix base addresses (buffer 0; buffer 1 adds bufStride bytes)
    const uint32_t aH0 = sm_u32(&sA[(size_t)0 * AR + (w * 16 + (sel & 1) * 8 + r8) * GLD + (sel >> 1) * 8]);
    const uint32_t aL0 = aH0 + (uint32_t)(AR * 2);
    const uint32_t wB0 = sm_u32(&sW[(size_t)(sel >> 1) * AR + r8 * GLD + (sel & 1) * 8]);
    const uint32_t bufStride = (uint32_t)(2 * AR * 2);   // bytes between buffers

    stage(0, 0);
    cp_commit();
    stage(64, 1);
    cp_commit();

    #pragma unroll
    for (int bf = 0; bf < 2; bf++) {
        if (bf == 0) cp_wait<1>(); else cp_wait<0>();
        __syncthreads();
        const uint32_t aH = aH0 + bf * bufStride;
        const uint32_t aL = aL0 + bf * bufStride;
        const uint32_t wB = wB0 + bf * bufStride;
        #pragma unroll
        for (int ks = 0; ks < 4; ks++) {
            uint32_t ah[4], al[4];
            ldsm4(ah, aH + ks * 32);
            ldsm4(al, aL + ks * 32);
            #pragma unroll
            for (int nb = 0; nb < 16; nb++) {
                uint32_t f[4];   // {wh0, wh1, wl0, wl1}
                ldsm4(f, wB + (uint32_t)(nb * 8 * GLD * 2) + ks * 32);
                mma16816(acc[nb], ah, f);
                mma16816(acc[nb], ah, f + 2);
                mma16816(acc[nb], al, f);
            }
        }
    }

    const int r0 = rowBase + w * 16 + g;
    const int r1 = r0 + 8;
    #pragma unroll
    for (int nb = 0; nb < 16; nb++) {
        int col = colBase + nb * 8 + c2;
        float bx = __ldg(&bias[col]);
        float by = __ldg(&bias[col + 1]);
        float v00 = (acc[nb][0] + bx) * oscale, v01 = (acc[nb][1] + by) * oscale;
        float v10 = (acc[nb][2] + bx) * oscale, v11 = (acc[nb][3] + by) * oscale;
        uint32_t h0, l0, h1, l1;
        splitpack(v00, v01, h0, l0);
        splitpack(v10, v11, h1, l1);
        *(uint32_t*)&Chi[(size_t)r0 * Pv + col] = h0;
        *(uint32_t*)&Clo[(size_t)r0 * Pv + col] = l0;
        *(uint32_t*)&Chi[(size_t)r1 * Pv + col] = h1;
        *(uint32_t*)&Clo[(size_t)r1 * Pv + col] = l1;
    }
}

// ---------------------------------------------------------------------------
// Flash attention (unchanged from R11): pre-split Q/K/V, ldmatrix frags,
// cp.async double buffering.
// ---------------------------------------------------------------------------
__global__ __launch_bounds__(256) void attn_mma(
    const int* __restrict__ mask, float* __restrict__ out)
{
    __shared__ half Ksm[2][2][64][40];   // [buf][hi/lo][key][e]
    __shared__ half Vsm[2][2][64][40];
    __shared__ float msk[Tv];

    const int tid  = threadIdx.x;
    const int w    = tid >> 5;
    const int lane = tid & 31;
    const int g    = lane >> 2;
    const int c2   = (lane & 3) * 2;
    const int r8   = lane & 7;
    const int sel  = lane >> 3;
    const int qt   = blockIdx.x;
    const int bmh  = blockIdx.y;
    const int h  = bmh & (Hv - 1);
    const int m_ = (bmh >> 3) & (Mv - 1);
    const int b  = bmh >> 7;

    const size_t base = ((size_t)b * Tv * Mv + m_) * (size_t)Pv + (size_t)h * Ev;
    const int qrow = qt * 128 + w * 16 + g;

    const int srow = tid >> 2;
    const int se8  = (tid & 3) * 8;

    uint32_t kbase[2], vbase[2];
    #pragma unroll
    for (int bf = 0; bf < 2; bf++) {
        kbase[bf] = sm_u32(&Ksm[bf][sel >> 1][r8][(sel & 1) * 8]);
        vbase[bf] = sm_u32(&Vsm[bf][sel >> 1][(sel & 1) * 8 + r8][0]);
    }

    for (int i = tid; i < Tv; i += 256)
        msk[i] = mask[(size_t)(b * Tv + i) * Mv + m_] ? 1.f : 0.f;

    uint32_t qh[2][4], ql[2][4];
    {
        const size_t o0 = base + (size_t)qrow * MP;
        const size_t o1 = o0 + (size_t)8 * MP;
        #pragma unroll
        for (int ks = 0; ks < 2; ks++) {
            int c = ks * 16 + c2;
            qh[ks][0] = *(const uint32_t*)&g_qh[o0 + c];
            qh[ks][1] = *(const uint32_t*)&g_qh[o1 + c];
            qh[ks][2] = *(const uint32_t*)&g_qh[o0 + c + 8];
            qh[ks][3] = *(const uint32_t*)&g_qh[o1 + c + 8];
            ql[ks][0] = *(const uint32_t*)&g_ql[o0 + c];
            ql[ks][1] = *(const uint32_t*)&g_ql[o1 + c];
            ql[ks][2] = *(const uint32_t*)&g_ql[o0 + c + 8];
            ql[ks][3] = *(const uint32_t*)&g_ql[o1 + c + 8];
        }
    }

    auto stage = [&](int kt, int bf) {
        size_t off = base + (size_t)(kt * 64 + srow) * MP + se8;
        cp16(sm_u32(&Ksm[bf][0][srow][se8]), &g_kh[off]);
        cp16(sm_u32(&Ksm[bf][1][srow][se8]), &g_kl[off]);
        cp16(sm_u32(&Vsm[bf][0][srow][se8]), &g_vh[off]);
        cp16(sm_u32(&Vsm[bf][1][srow][se8]), &g_vl[off]);
    };

    float O[4][4] = {};
    float mrow0 = -1e30f, mrow1 = -1e30f;
    float lrow0 = 0.f,    lrow1 = 0.f;

    stage(0, 0);
    cp_commit();

    for (int kt = 0; kt < 8; kt++) {
        const int cur = kt & 1;
        if (kt < 7) {
            stage(kt + 1, cur ^ 1);
            cp_commit();
            cp_wait<1>();
        } else {
            cp_wait<0>();
        }
        __syncthreads();

        float S[8][4];
        #pragma unroll
        for (int nb = 0; nb < 8; nb++) {
            S[nb][0] = S[nb][1] = S[nb][2] = S[nb][3] = 0.f;
            #pragma unroll
            for (int ks = 0; ks < 2; ks++) {
                uint32_t f[4];
                ldsm4(f, kbase[cur] + (uint32_t)(nb * 640 + ks * 32));
                mma16816(S[nb], qh[ks], f);
                mma16816(S[nb], qh[ks], f + 2);
                mma16816(S[nb], ql[ks], f);
            }
        }

        const float* mrow = &msk[kt * 64];
        float mt0 = -1e30f, mt1 = -1e30f;
        #pragma unroll
        for (int nb = 0; nb < 8; nb++) {
            float mk0 = mrow[nb * 8 + c2];
            float mk1 = mrow[nb * 8 + c2 + 1];
            S[nb][0] = (mk0 != 0.f) ? S[nb][0] : -1e30f;
            S[nb][1] = (mk1 != 0.f) ? S[nb][1] : -1e30f;
            S[nb][2] = (mk0 != 0.f) ? S[nb][2] : -1e30f;
            S[nb][3] = (mk1 != 0.f) ? S[nb][3] : -1e30f;
            mt0 = fmaxf(mt0, fmaxf(S[nb][0], S[nb][1]));
            mt1 = fmaxf(mt1, fmaxf(S[nb][2], S[nb][3]));
        }
        mt0 = fmaxf(mt0, __shfl_xor_sync(0xffffffffu, mt0, 1));
        mt0 = fmaxf(mt0, __shfl_xor_sync(0xffffffffu, mt0, 2));
        mt1 = fmaxf(mt1, __shfl_xor_sync(0xffffffffu, mt1, 1));
        mt1 = fmaxf(mt1, __shfl_xor_sync(0xffffffffu, mt1, 2));

        float mn0 = fmaxf(mrow0, mt0), mn1 = fmaxf(mrow1, mt1);
        float a0 = __expf(mrow0 - mn0), a1 = __expf(mrow1 - mn1);
        mrow0 = mn0; mrow1 = mn1;

        float rs0 = 0.f, rs1 = 0.f;
        #pragma unroll
        for (int nb = 0; nb < 8; nb++) {
            S[nb][0] = __expf(S[nb][0] - mn0);
            S[nb][1] = __expf(S[nb][1] - mn0);
            S[nb][2] = __expf(S[nb][2] - mn1);
            S[nb][3] = __expf(S[nb][3] - mn1);
            rs0 += S[nb][0] + S[nb][1];
            rs1 += S[nb][2] + S[nb][3];
        }
        rs0 += __shfl_xor_sync(0xffffffffu, rs0, 1);
        rs0 += __shfl_xor_sync(0xffffffffu, rs0, 2);
        rs1 += __shfl_xor_sync(0xffffffffu, rs1, 1);
        rs1 += __shfl_xor_sync(0xffffffffu, rs1, 2);
        lrow0 = lrow0 * a0 + rs0;
        lrow1 = lrow1 * a1 + rs1;
        #pragma unroll
        for (int eb = 0; eb < 4; eb++) {
            O[eb][0] *= a0; O[eb][1] *= a0;
            O[eb][2] *= a1; O[eb][3] *= a1;
        }

        #pragma unroll
        for (int kb = 0; kb < 4; kb++) {
            uint32_t ph[4], pl[4];
            splitpack(S[2 * kb][0],     S[2 * kb][1],     ph[0], pl[0]);
            splitpack(S[2 * kb][2],     S[2 * kb][3],     ph[1], pl[1]);
            splitpack(S[2 * kb + 1][0], S[2 * kb + 1][1], ph[2], pl[2]);
            splitpack(S[2 * kb + 1][2], S[2 * kb + 1][3], ph[3], pl[3]);
            #pragma unroll
            for (int eb = 0; eb < 4; eb++) {
                uint32_t f[4];
                ldsm4t(f, vbase[cur] + (uint32_t)(kb * 1280 + eb * 16));
                mma16816(O[eb], ph, f);
                mma16816(O[eb], ph, f + 2);
                mma16816(O[eb], pl, f);
            }
        }
        __syncthreads();
    }

    float inv0 = (mrow0 > -1e29f) ? (1.f / lrow0) : 0.f;
    float inv1 = (mrow1 > -1e29f) ? (1.f / lrow1) : 0.f;
    float* o0 = &out[base + (size_t)qrow * MP];
    float* o1 = o0 + (size_t)8 * MP;
    #pragma unroll
    for (int eb = 0; eb < 4; eb++) {
        int e = eb * 8 + c2;
        o0[e]     = O[eb][0] * inv0;
        o0[e + 1] = O[eb][1] * inv0;
        o1[e]     = O[eb][2] * inv1;
        o1[e + 1] = O[eb][3] * inv1;
    }
}

// ---------------------------------------------------------------------------
// Inputs (metadata order): inp, mask, Wq, bq, Wk, bk, Wv, bv
// ---------------------------------------------------------------------------
extern "C" void kernel_launch(void* const* d_in, const int* in_sizes, int n_in,
                              void* d_out, int out_size)
{
    (void)in_sizes; (void)n_in; (void)out_size;
    const float* inp  = (const float*)d_in[0];
    const int*   mask = (const int*)d_in[1];
    const float* Wq = (const float*)d_in[2];
    const float* bq = (const float*)d_in[3];
    const float* Wk = (const float*)d_in[4];
    const float* bk = (const float*)d_in[5];
    const float* Wv = (const float*)d_in[6];
    const float* bv = (const float*)d_in[7];
    float* out = (float*)d_out;

    static bool attr_done = false;
    if (!attr_done) {
        cudaFuncSetAttribute(qkv_gemm_mma, cudaFuncAttributeMaxDynamicSharedMemorySize, GEMM_SMEM);
        attr_done = true;
    }

    prep_a<<<(ROWS * Dv / 4) / 256, 256>>>(inp);
    prep_w<<<96, 256>>>(Wq, Wk, Wv);

    dim3 ggrid(ROWS / 128, Pv / 128, 3);   // (512, 2, 3)
    qkv_gemm_mma<<<ggrid, 256, GEMM_SMEM>>>(bq, bk, bv);

    dim3 agrid(Tv / 128, Bv * Mv * Hv);    // (4, 1024)
    attn_mma<<<agrid, 256>>>(mask, out);
}

// round 14
// speedup vs baseline: 1.8530x; 1.3217x over previous
#include <cuda_runtime.h>
#include <cuda_fp16.h>
#include <cstdint>

#define Bv 8
#define Tv 512
#define Mv 16
#define Dv 128
#define Pv 256
#define Hv 8
#define Ev 32
#define ROWS (Bv*Tv*Mv)   // 65536
#define MP 4096           // Mv*Pv: element stride between consecutive t (original layout)

// Q in [bm][t][P] layout; K/V COMPACTED per (b,m) in [bm][key][P] layout.
__device__ half g_qh[(size_t)ROWS * Pv];
__device__ half g_ql[(size_t)ROWS * Pv];
__device__ half g_kh[(size_t)ROWS * Pv];
__device__ half g_kl[(size_t)ROWS * Pv];
__device__ half g_vh[(size_t)ROWS * Pv];
__device__ half g_vl[(size_t)ROWS * Pv];
// Pre-split GEMM inputs: A (inp) hi/lo, W transposed [which][c][k] hi/lo.
__device__ half g_ah[(size_t)ROWS * Dv];
__device__ half g_al[(size_t)ROWS * Dv];
__device__ half g_wh[3 * Pv * Dv];
__device__ half g_wl[3 * Pv * Dv];
// Compaction metadata
__device__ int g_pos[Bv * Mv * Tv];   // compacted pos per (bm,t); -1 if masked
__device__ int g_nv[Bv * Mv];         // valid count per (bm)

__device__ __forceinline__ void split2(float x, half& hi, half& lo) {
    hi = __float2half_rn(x);
    lo = __float2half_rn(x - __half2float(hi));
}
__device__ __forceinline__ void splitpack(float x, float y, uint32_t& hi, uint32_t& lo) {
    half hx, lx, hy, ly;
    split2(x, hx, lx);
    split2(y, hy, ly);
    __half2 h = __halves2half2(hx, hy);
    __half2 l = __halves2half2(lx, ly);
    hi = *(uint32_t*)&h;
    lo = *(uint32_t*)&l;
}
__device__ __forceinline__ void mma16816(float* c, const uint32_t* a, const uint32_t* b) {
    asm volatile(
        "mma.sync.aligned.m16n8k16.row.col.f32.f16.f16.f32 "
        "{%0,%1,%2,%3}, {%4,%5,%6,%7}, {%8,%9}, {%0,%1,%2,%3};\n"
        : "+f"(c[0]), "+f"(c[1]), "+f"(c[2]), "+f"(c[3])
        : "r"(a[0]), "r"(a[1]), "r"(a[2]), "r"(a[3]), "r"(b[0]), "r"(b[1]));
}
__device__ __forceinline__ void ldsm4(uint32_t* r, uint32_t a) {
    asm volatile("ldmatrix.sync.aligned.m8n8.x4.shared.b16 {%0,%1,%2,%3}, [%4];"
        : "=r"(r[0]), "=r"(r[1]), "=r"(r[2]), "=r"(r[3]) : "r"(a));
}
__device__ __forceinline__ void ldsm4t(uint32_t* r, uint32_t a) {
    asm volatile("ldmatrix.sync.aligned.m8n8.x4.trans.shared.b16 {%0,%1,%2,%3}, [%4];"
        : "=r"(r[0]), "=r"(r[1]), "=r"(r[2]), "=r"(r[3]) : "r"(a));
}
__device__ __forceinline__ uint32_t sm_u32(const void* p) {
    return (uint32_t)__cvta_generic_to_shared(p);
}
__device__ __forceinline__ void cp16(uint32_t dst, const void* src) {
    asm volatile("cp.async.cg.shared.global [%0], [%1], 16;" :: "r"(dst), "l"(src));
}
__device__ __forceinline__ void cp_commit() {
    asm volatile("cp.async.commit_group;");
}
template<int N>
__device__ __forceinline__ void cp_wait() {
    asm volatile("cp.async.wait_group %0;" :: "n"(N));
}

// ===========================================================================
// Prep kernels
// ===========================================================================
__global__ __launch_bounds__(256) void prep_a(const float* __restrict__ inp)
{
    size_t idx = (size_t)blockIdx.x * 256 + threadIdx.x;
    float4 a = *(const float4*)&inp[idx * 4];
    uint32_t h0, l0, h1, l1;
    splitpack(a.x, a.y, h0, l0);
    splitpack(a.z, a.w, h1, l1);
    *(uint32_t*)&g_ah[idx * 4]     = h0;
    *(uint32_t*)&g_ah[idx * 4 + 2] = h1;
    *(uint32_t*)&g_al[idx * 4]     = l0;
    *(uint32_t*)&g_al[idx * 4 + 2] = l1;
}

__global__ __launch_bounds__(256) void prep_w(
    const float* __restrict__ Wq, const float* __restrict__ Wk, const float* __restrict__ Wv)
{
    int t = blockIdx.x * 256 + threadIdx.x;
    int which = t / 8192;
    int rem = t - which * 8192;
    int c  = rem >> 5;
    int k4 = (rem & 31) * 4;
    const float* W = (which == 0) ? Wq : (which == 1) ? Wk : Wv;
    float w0 = W[(size_t)(k4 + 0) * Pv + c];
    float w1 = W[(size_t)(k4 + 1) * Pv + c];
    float w2 = W[(size_t)(k4 + 2) * Pv + c];
    float w3 = W[(size_t)(k4 + 3) * Pv + c];
    uint32_t h0, l0, h1, l1;
    splitpack(w0, w1, h0, l0);
    splitpack(w2, w3, h1, l1);
    size_t off = ((size_t)which * Pv + c) * Dv + k4;
    *(uint32_t*)&g_wh[off]     = h0;
    *(uint32_t*)&g_wh[off + 2] = h1;
    *(uint32_t*)&g_wl[off]     = l0;
    *(uint32_t*)&g_wl[off + 2] = l1;
}

// Mask prefix scan per (b,m) + zero-pad compacted K/V tail to tile boundary.
__global__ __launch_bounds__(512) void prep_mask(const int* __restrict__ mask)
{
    __shared__ int wsum[16], woff[16], total_s;
    const int bm = blockIdx.x;             // b*16 + m
    const int b = bm >> 4, m = bm & 15;
    const int t = threadIdx.x;
    const int lane = t & 31, wid = t >> 5;

    int valid = mask[(size_t)(b * Tv + t) * Mv + m] ? 1 : 0;
    unsigned bal = __ballot_sync(0xffffffffu, valid);
    int wpre = __popc(bal & ((1u << lane) - 1u));
    if (lane == 31) wsum[wid] = wpre + valid;
    __syncthreads();
    if (t == 0) {
        int s = 0;
        for (int i = 0; i < 16; i++) { woff[i] = s; s += wsum[i]; }
        total_s = s;
    }
    __syncthreads();
    const int total = total_s;
    int pos = woff[wid] + wpre;
    g_pos[bm * Tv + t] = valid ? pos : -1;
    if (t == 0) g_nv[bm] = total;

    // zero-pad rows [total, padend) of compacted K/V
    int padend = (total + 63) & ~63;
    int npad = padend - total;
    uint4 z = make_uint4(0, 0, 0, 0);
    for (int i = t; i < npad * (Pv / 8); i += 512) {
        int rr = total + i / (Pv / 8);
        int e8 = (i % (Pv / 8)) * 8;
        size_t off = ((size_t)bm * Tv + rr) * Pv + e8;
        *(uint4*)&g_kh[off] = z;
        *(uint4*)&g_kl[off] = z;
        *(uint4*)&g_vh[off] = z;
        *(uint4*)&g_vl[off] = z;
    }
}

// ===========================================================================
// QKV GEMM: pre-split inputs, cp.async double-buffered tiles, ldmatrix frags.
// Epilogue: Q -> [bm][t][P]; K/V -> compacted [bm][pos][P] (masked rows dropped).
// ===========================================================================
#define GLD 72
#define GEMM_SMEM (8 * 128 * GLD * 2)   // 147456 B

__global__ __launch_bounds__(256) void qkv_gemm_mma(
    const float* __restrict__ bq, const float* __restrict__ bk, const float* __restrict__ bv)
{
    extern __shared__ half sm[];
    half* sA = sm;
    half* sW = sA + 4 * 128 * GLD;

    const int which = blockIdx.z;
    const float* __restrict__ bias = (which == 0) ? bq : (which == 1) ? bk : bv;
    half* __restrict__ Chi         = (which == 0) ? g_qh : (which == 1) ? g_kh : g_vh;
    half* __restrict__ Clo         = (which == 0) ? g_ql : (which == 1) ? g_kl : g_vl;
    const float oscale = (which == 0) ? 0.17677669529663687f : 1.0f;

    const int tid  = threadIdx.x;
    const int w    = tid >> 5;
    const int lane = tid & 31;
    const int g    = lane >> 2;
    const int c2   = (lane & 3) * 2;
    const int r8   = lane & 7;
    const int sel  = lane >> 3;
    const int rowBase = blockIdx.x * 128;
    const int colBase = blockIdx.y * 128;

    const size_t AR = 128 * GLD;

    auto stage = [&](int kk, int bf) {
        #pragma unroll
        for (int it = 0; it < 4; it++) {
            int i  = tid + it * 256;
            int r  = i >> 3;
            int k8 = (i & 7) * 8;
            size_t asrc = (size_t)(rowBase + r) * Dv + kk + k8;
            cp16(sm_u32(&sA[(size_t)(bf * 2 + 0) * AR + r * GLD + k8]), &g_ah[asrc]);
            cp16(sm_u32(&sA[(size_t)(bf * 2 + 1) * AR + r * GLD + k8]), &g_al[asrc]);
            size_t wsrc = ((size_t)which * Pv + colBase + r) * Dv + kk + k8;
            cp16(sm_u32(&sW[(size_t)(bf * 2 + 0) * AR + r * GLD + k8]), &g_wh[wsrc]);
            cp16(sm_u32(&sW[(size_t)(bf * 2 + 1) * AR + r * GLD + k8]), &g_wl[wsrc]);
        }
    };

    float acc[16][4];
    #pragma unroll
    for (int nb = 0; nb < 16; nb++)
        acc[nb][0] = acc[nb][1] = acc[nb][2] = acc[nb][3] = 0.f;

    const uint32_t aH0 = sm_u32(&sA[(size_t)0 * AR + (w * 16 + (sel & 1) * 8 + r8) * GLD + (sel >> 1) * 8]);
    const uint32_t aL0 = aH0 + (uint32_t)(AR * 2);
    const uint32_t wB0 = sm_u32(&sW[(size_t)(sel >> 1) * AR + r8 * GLD + (sel & 1) * 8]);
    const uint32_t bufStride = (uint32_t)(2 * AR * 2);

    stage(0, 0);
    cp_commit();
    stage(64, 1);
    cp_commit();

    #pragma unroll
    for (int bf = 0; bf < 2; bf++) {
        if (bf == 0) cp_wait<1>(); else cp_wait<0>();
        __syncthreads();
        const uint32_t aH = aH0 + bf * bufStride;
        const uint32_t aL = aL0 + bf * bufStride;
        const uint32_t wB = wB0 + bf * bufStride;
        #pragma unroll
        for (int ks = 0; ks < 4; ks++) {
            uint32_t ah[4], al[4];
            ldsm4(ah, aH + ks * 32);
            ldsm4(al, aL + ks * 32);
            #pragma unroll
            for (int nb = 0; nb < 16; nb++) {
                uint32_t f[4];
                ldsm4(f, wB + (uint32_t)(nb * 8 * GLD * 2) + ks * 32);
                mma16816(acc[nb], ah, f);
                mma16816(acc[nb], ah, f + 2);
                mma16816(acc[nb], al, f);
            }
        }
    }

    // epilogue: row decomposition r = (b*Tv + t)*Mv + m
    const int r0 = rowBase + w * 16 + g;
    const int r1 = r0 + 8;
    const int bm0 = ((r0 >> 13) << 4) | (r0 & 15);
    const int t0  = (r0 >> 4) & 511;
    const int bm1 = ((r1 >> 13) << 4) | (r1 & 15);
    const int t1  = (r1 >> 4) & 511;

    size_t dst0, dst1;
    bool wr0 = true, wr1 = true;
    if (which == 0) {
        dst0 = ((size_t)bm0 * Tv + t0) * Pv;
        dst1 = ((size_t)bm1 * Tv + t1) * Pv;
    } else {
        int p0 = g_pos[bm0 * Tv + t0];
        int p1 = g_pos[bm1 * Tv + t1];
        wr0 = (p0 >= 0);
        wr1 = (p1 >= 0);
        dst0 = ((size_t)bm0 * Tv + (wr0 ? p0 : 0)) * Pv;
        dst1 = ((size_t)bm1 * Tv + (wr1 ? p1 : 0)) * Pv;
    }

    #pragma unroll
    for (int nb = 0; nb < 16; nb++) {
        int col = colBase + nb * 8 + c2;
        float bx = __ldg(&bias[col]);
        float by = __ldg(&bias[col + 1]);
        float v00 = (acc[nb][0] + bx) * oscale, v01 = (acc[nb][1] + by) * oscale;
        float v10 = (acc[nb][2] + bx) * oscale, v11 = (acc[nb][3] + by) * oscale;
        uint32_t h0, l0, h1, l1;
        splitpack(v00, v01, h0, l0);
        splitpack(v10, v11, h1, l1);
        if (wr0) {
            *(uint32_t*)&Chi[dst0 + col] = h0;
            *(uint32_t*)&Clo[dst0 + col] = l0;
        }
        if (wr1) {
            *(uint32_t*)&Chi[dst1 + col] = h1;
            *(uint32_t*)&Clo[dst1 + col] = l1;
        }
    }
}

// ---------------------------------------------------------------------------
// Flash attention over COMPACTED keys: dynamic tile count ceil(nv/64),
// mask = register compare (j < nv). cp.async double buffering + ldmatrix.
// ---------------------------------------------------------------------------
__global__ __launch_bounds__(256) void attn_mma(float* __restrict__ out)
{
    __shared__ half Ksm[2][2][64][40];   // [buf][hi/lo][key][e]
    __shared__ half Vsm[2][2][64][40];

    const int tid  = threadIdx.x;
    const int w    = tid >> 5;
    const int lane = tid & 31;
    const int g    = lane >> 2;
    const int c2   = (lane & 3) * 2;
    const int r8   = lane & 7;
    const int sel  = lane >> 3;
    const int qt   = blockIdx.x;
    const int bmh  = blockIdx.y;
    const int h  = bmh & (Hv - 1);
    const int m_ = (bmh >> 3) & (Mv - 1);
    const int b  = bmh >> 7;
    const int bm = b * Mv + m_;

    const size_t qbase   = ((size_t)bm * Tv) * Pv + (size_t)h * Ev;   // Q/K/V layout
    const size_t outbase = ((size_t)b * Tv * Mv + m_) * (size_t)Pv + (size_t)h * Ev;
    const int qrow = qt * 128 + w * 16 + g;

    const int nv = g_nv[bm];
    const int ntiles = (nv + 63) >> 6;

    const int srow = tid >> 2;
    const int se8  = (tid & 3) * 8;

    uint32_t kbase[2], vbase[2];
    #pragma unroll
    for (int bf = 0; bf < 2; bf++) {
        kbase[bf] = sm_u32(&Ksm[bf][sel >> 1][r8][(sel & 1) * 8]);
        vbase[bf] = sm_u32(&Vsm[bf][sel >> 1][(sel & 1) * 8 + r8][0]);
    }

    // ---- Q fragments (contiguous Pv-stride rows) ----
    uint32_t qh[2][4], ql[2][4];
    {
        const size_t o0 = qbase + (size_t)qrow * Pv;
        const size_t o1 = o0 + (size_t)8 * Pv;
        #pragma unroll
        for (int ks = 0; ks < 2; ks++) {
            int c = ks * 16 + c2;
            qh[ks][0] = *(const uint32_t*)&g_qh[o0 + c];
            qh[ks][1] = *(const uint32_t*)&g_qh[o1 + c];
            qh[ks][2] = *(const uint32_t*)&g_qh[o0 + c + 8];
            qh[ks][3] = *(const uint32_t*)&g_qh[o1 + c + 8];
            ql[ks][0] = *(const uint32_t*)&g_ql[o0 + c];
            ql[ks][1] = *(const uint32_t*)&g_ql[o1 + c];
            ql[ks][2] = *(const uint32_t*)&g_ql[o0 + c + 8];
            ql[ks][3] = *(const uint32_t*)&g_ql[o1 + c + 8];
        }
    }

    auto stage = [&](int kt, int bf) {
        size_t off = qbase + (size_t)(kt * 64 + srow) * Pv + se8;
        cp16(sm_u32(&Ksm[bf][0][srow][se8]), &g_kh[off]);
        cp16(sm_u32(&Ksm[bf][1][srow][se8]), &g_kl[off]);
        cp16(sm_u32(&Vsm[bf][0][srow][se8]), &g_vh[off]);
        cp16(sm_u32(&Vsm[bf][1][srow][se8]), &g_vl[off]);
    };

    float O[4][4] = {};
    float mrow0 = -1e30f, mrow1 = -1e30f;
    float lrow0 = 0.f,    lrow1 = 0.f;

    if (ntiles > 0) {
        stage(0, 0);
        cp_commit();
    }

    for (int kt = 0; kt < ntiles; kt++) {
        const int cur = kt & 1;
        if (kt + 1 < ntiles) {
            stage(kt + 1, cur ^ 1);
            cp_commit();
            cp_wait<1>();
        } else {
            cp_wait<0>();
        }
        __syncthreads();

        float S[8][4];
        #pragma unroll
        for (int nb = 0; nb < 8; nb++) {
            S[nb][0] = S[nb][1] = S[nb][2] = S[nb][3] = 0.f;
            #pragma unroll
            for (int ks = 0; ks < 2; ks++) {
                uint32_t f[4];
                ldsm4(f, kbase[cur] + (uint32_t)(nb * 640 + ks * 32));
                mma16816(S[nb], qh[ks], f);
                mma16816(S[nb], qh[ks], f + 2);
                mma16816(S[nb], ql[ks], f);
            }
        }

        // ---- validity (j < nv) + online softmax ----
        const int jb = kt * 64;
        float mt0 = -1e30f, mt1 = -1e30f;
        #pragma unroll
        for (int nb = 0; nb < 8; nb++) {
            bool v0 = (jb + nb * 8 + c2)     < nv;
            bool v1 = (jb + nb * 8 + c2 + 1) < nv;
            S[nb][0] = v0 ? S[nb][0] : -1e30f;
            S[nb][1] = v1 ? S[nb][1] : -1e30f;
            S[nb][2] = v0 ? S[nb][2] : -1e30f;
            S[nb][3] = v1 ? S[nb][3] : -1e30f;
            mt0 = fmaxf(mt0, fmaxf(S[nb][0], S[nb][1]));
            mt1 = fmaxf(mt1, fmaxf(S[nb][2], S[nb][3]));
        }
        mt0 = fmaxf(mt0, __shfl_xor_sync(0xffffffffu, mt0, 1));
        mt0 = fmaxf(mt0, __shfl_xor_sync(0xffffffffu, mt0, 2));
        mt1 = fmaxf(mt1, __shfl_xor_sync(0xffffffffu, mt1, 1));
        mt1 = fmaxf(mt1, __shfl_xor_sync(0xffffffffu, mt1, 2));

        float mn0 = fmaxf(mrow0, mt0), mn1 = fmaxf(mrow1, mt1);
        float a0 = __expf(mrow0 - mn0), a1 = __expf(mrow1 - mn1);
        mrow0 = mn0; mrow1 = mn1;

        float rs0 = 0.f, rs1 = 0.f;
        #pragma unroll
        for (int nb = 0; nb < 8; nb++) {
            S[nb][0] = __expf(S[nb][0] - mn0);
            S[nb][1] = __expf(S[nb][1] - mn0);
            S[nb][2] = __expf(S[nb][2] - mn1);
            S[nb][3] = __expf(S[nb][3] - mn1);
            rs0 += S[nb][0] + S[nb][1];
            rs1 += S[nb][2] + S[nb][3];
        }
        rs0 += __shfl_xor_sync(0xffffffffu, rs0, 1);
        rs0 += __shfl_xor_sync(0xffffffffu, rs0, 2);
        rs1 += __shfl_xor_sync(0xffffffffu, rs1, 1);
        rs1 += __shfl_xor_sync(0xffffffffu, rs1, 2);
        lrow0 = lrow0 * a0 + rs0;
        lrow1 = lrow1 * a1 + rs1;
        #pragma unroll
        for (int eb = 0; eb < 4; eb++) {
            O[eb][0] *= a0; O[eb][1] *= a0;
            O[eb][2] *= a1; O[eb][3] *= a1;
        }

        #pragma unroll
        for (int kb = 0; kb < 4; kb++) {
            uint32_t ph[4], pl[4];
            splitpack(S[2 * kb][0],     S[2 * kb][1],     ph[0], pl[0]);
            splitpack(S[2 * kb][2],     S[2 * kb][3],     ph[1], pl[1]);
            splitpack(S[2 * kb + 1][0], S[2 * kb + 1][1], ph[2], pl[2]);
            splitpack(S[2 * kb + 1][2], S[2 * kb + 1][3], ph[3], pl[3]);
            #pragma unroll
            for (int eb = 0; eb < 4; eb++) {
                uint32_t f[4];
                ldsm4t(f, vbase[cur] + (uint32_t)(kb * 1280 + eb * 16));
                mma16816(O[eb], ph, f);
                mma16816(O[eb], ph, f + 2);
                mma16816(O[eb], pl, f);
            }
        }
        __syncthreads();
    }

    float inv0 = (mrow0 > -1e29f) ? (1.f / lrow0) : 0.f;
    float inv1 = (mrow1 > -1e29f) ? (1.f / lrow1) : 0.f;
    float* o0 = &out[outbase + (size_t)qrow * MP];
    float* o1 = o0 + (size_t)8 * MP;
    #pragma unroll
    for (int eb = 0; eb < 4; eb++) {
        int e = eb * 8 + c2;
        o0[e]     = O[eb][0] * inv0;
        o0[e + 1] = O[eb][1] * inv0;
        o1[e]     = O[eb][2] * inv1;
        o1[e + 1] = O[eb][3] * inv1;
    }
}

// ---------------------------------------------------------------------------
// Inputs (metadata order): inp, mask, Wq, bq, Wk, bk, Wv, bv
// ---------------------------------------------------------------------------
extern "C" void kernel_launch(void* const* d_in, const int* in_sizes, int n_in,
                              void* d_out, int out_size)
{
    (void)in_sizes; (void)n_in; (void)out_size;
    const float* inp  = (const float*)d_in[0];
    const int*   mask = (const int*)d_in[1];
    const float* Wq = (const float*)d_in[2];
    const float* bq = (const float*)d_in[3];
    const float* Wk = (const float*)d_in[4];
    const float* bk = (const float*)d_in[5];
    const float* Wv = (const float*)d_in[6];
    const float* bv = (const float*)d_in[7];
    float* out = (float*)d_out;

    static bool attr_done = false;
    if (!attr_done) {
        cudaFuncSetAttribute(qkv_gemm_mma, cudaFuncAttributeMaxDynamicSharedMemorySize, GEMM_SMEM);
        attr_done = true;
    }

    prep_a<<<(ROWS * Dv / 4) / 256, 256>>>(inp);
    prep_w<<<96, 256>>>(Wq, Wk, Wv);
    prep_mask<<<Bv * Mv, 512>>>(mask);

    dim3 ggrid(ROWS / 128, Pv / 128, 3);   // (512, 2, 3)
    qkv_gemm_mma<<<ggrid, 256, GEMM_SMEM>>>(bq, bk, bv);

    dim3 agrid(Tv / 128, Bv * Mv * Hv);    // (4, 1024)
    attn_mma<<<agrid, 256>>>(out);
}